// round 7
// baseline (speedup 1.0000x reference)
#include <cuda_runtime.h>
#include <cuda_fp16.h>
#include <cstdint>

#define NGR   20000
#define NODES 7
#define PAD   8
#define MP    (NGR*PAD)        // 160000 padded rows
#define NN    (NGR*NODES)      // 140000 real nodes
#define HID   256
#define NOPS  5

#define BM 128                 // 16 graphs (8 padded rows each)
#define BN 128
#define BK 16
#define STAGES (HID/BK)        // 16

#define ROWB  48               // bytes per smem row (16 fp16 data + pad; conflict-free, 16B-mult)
#define ACOMP (128*ROWB)       // 6144 B per split component
#define BOFF  (2*ACOMP)        // 12288 (A: 2 comps)
#define STAGE (4*ACOMP)        // 24576 per stage (A0,A1,B0,B1)
#define SMEM_DYN (128*132*4)   // 67584: epilogue staging dominates (> 2*STAGE = 49152)

#define WSCALE     64.0f
#define INV_WSCALE 0.015625f

// ---------------- device globals (no allocs allowed) ----------------
__device__ float g_H1p[(size_t)MP*HID];        // padded; row 7 of each graph never read as output
__device__ float g_H2p[(size_t)MP*HID];
__device__ __half g_Wsp[2][2*HID*HID];         // per-layer 2-way fp16 split of 64*W, [n][k] layout

typedef uint32_t u32;

// ---------------- PTX helpers (all plain sm_80-class features) ----------------
__device__ __forceinline__ u32 s2u(const void* p){
    u32 a;
    asm("{ .reg .u64 t; cvta.to.shared.u64 t, %1; cvt.u32.u64 %0, t; }" : "=r"(a) : "l"(p));
    return a;
}
__device__ __forceinline__ void cp16(u32 dst, const void* src){
    asm volatile("cp.async.cg.shared.global [%0], [%1], 16;" :: "r"(dst), "l"(src));
}
#define CPCOMMIT() asm volatile("cp.async.commit_group;")
#define CPWAIT0()  asm volatile("cp.async.wait_group 0;" ::: "memory")

__device__ __forceinline__ void ldsm_x4(u32& r0,u32& r1,u32& r2,u32& r3, u32 a){
    asm volatile("ldmatrix.sync.aligned.m8n8.x4.shared.b16 {%0,%1,%2,%3}, [%4];"
                 : "=r"(r0),"=r"(r1),"=r"(r2),"=r"(r3) : "r"(a));
}
__device__ __forceinline__ void mma16816(float* c, const u32* a, const u32* b){
    asm volatile("mma.sync.aligned.m16n8k16.row.col.f32.f16.f16.f32 "
        "{%0,%1,%2,%3}, {%4,%5,%6,%7}, {%8,%9}, {%0,%1,%2,%3};"
        : "+f"(c[0]),"+f"(c[1]),"+f"(c[2]),"+f"(c[3])
        : "r"(a[0]),"r"(a[1]),"r"(a[2]),"r"(a[3]), "r"(b[0]),"r"(b[1]));
}
__device__ __forceinline__ void sts128(u32 a, u32 x, u32 y, u32 z, u32 w){
    asm volatile("st.shared.v4.b32 [%0], {%1,%2,%3,%4};" :: "r"(a), "r"(x),"r"(y),"r"(z),"r"(w) : "memory");
}
// fp32 -> 2-way fp16 split of adjacent pair (lo=x, hi=y), packed f16x2
__device__ __forceinline__ void split2h(float x, float y, u32& p0, u32& p1){
    u32 hx = (u32)__half_as_ushort(__float2half_rn(x));
    u32 hy = (u32)__half_as_ushort(__float2half_rn(y));
    p0 = hx | (hy << 16);
    float rx = x - __half2float(__ushort_as_half((unsigned short)hx));
    float ry = y - __half2float(__ushort_as_half((unsigned short)hy));
    u32 gx = (u32)__half_as_ushort(__float2half_rn(rx));
    u32 gy = (u32)__half_as_ushort(__float2half_rn(ry));
    p1 = gx | (gy << 16);
}

// ============ HMMA GEMM (fp16x2, 4-pass exact) + fused GCN agg + bias + relu ============
__global__ __launch_bounds__(256, 2)
void gemm_mma(const float* __restrict__ A, const __half* __restrict__ Wsp,
              const float* __restrict__ bias, float* __restrict__ H, int padmap)
{
    extern __shared__ __align__(128) char smem[];
    const u32 sb = s2u(smem);

    const int tid  = threadIdx.x;
    const int lane = tid & 31;
    const int warp = tid >> 5;
    const int wm = warp >> 1;          // 0..3  (M: 32-row slab)
    const int wn = warp & 1;           // 0..1  (N: 64-col slab)
    const int m0 = blockIdx.y * BM;
    const int n0 = blockIdx.x * BN;

    // ---- A global source row for this thread (loads 8 floats: row tid>>1, cols half*8..+7)
    const int  arow_i = tid >> 1;
    const int  half   = tid & 1;
    const float* arow;
    if (padmap) {                       // layer 1: unpadded 7-row graphs
        int pr = m0 + arow_i, g = pr >> 3, j = pr & 7;
        arow = (j < NODES) ? (A + (size_t)(g*NODES + j) * HID) : nullptr;
    } else {
        arow = A + (size_t)(m0 + arow_i) * HID;
    }

    float4 av0, av1;

    #define LOAD_A(k0) do {                                                     \
        if (arow) { av0 = *(const float4*)(arow + (k0) + half*8);               \
                    av1 = *(const float4*)(arow + (k0) + half*8 + 4); }         \
        else      { av0 = make_float4(0.f,0.f,0.f,0.f); av1 = av0; }            \
    } while(0)

    #define STS_A(stb) do {                                                     \
        u32 p0[4], p1[4];                                                       \
        split2h(av0.x, av0.y, p0[0], p1[0]);                                    \
        split2h(av0.z, av0.w, p0[1], p1[1]);                                    \
        split2h(av1.x, av1.y, p0[2], p1[2]);                                    \
        split2h(av1.z, av1.w, p0[3], p1[3]);                                    \
        u32 ad = (stb) + arow_i*ROWB + half*16;                                 \
        sts128(ad,         p0[0], p0[1], p0[2], p0[3]);                         \
        sts128(ad + ACOMP, p1[0], p1[1], p1[2], p1[3]);                         \
    } while(0)

    #define CP_B(stb, k0) do {                                                  \
        _Pragma("unroll")                                                       \
        for (int i = 0; i < 2; i++) {                                           \
            int c = tid + 256*i;                                                \
            int comp = c >> 8, rem = c & 255, n = rem >> 1, hf = rem & 1;       \
            u32 dst = (stb) + BOFF + comp*ACOMP + n*ROWB + hf*16;               \
            const __half* src = Wsp + (size_t)comp*HID*HID                      \
                                + (size_t)(n0 + n)*HID + (k0) + hf*8;           \
            cp16(dst, src);                                                     \
        }                                                                       \
        CPCOMMIT();                                                             \
    } while(0)

    // ---- prologue: stage 0
    CP_B(sb, 0);
    LOAD_A(0);
    STS_A(sb);
    CPWAIT0();
    __syncthreads();

    float acc[64];
    #pragma unroll
    for (int i = 0; i < 64; i++) acc[i] = 0.f;

    // ldmatrix lane addressing (constant across stages)
    const int a_r   = wm*32 + (lane & 15);
    const int a_ch  = lane >> 4;
    const int b_row = wn*64 + (lane & 7) + (lane >> 4) * 8;   // lanes 16-31 -> next n-tile
    const int b_ch  = (lane >> 3) & 1;

    #pragma unroll 1
    for (int s = 0; s < STAGES; s++) {
        const u32 cur = sb + (u32)(s & 1) * STAGE;
        const u32 nxt = sb + (u32)((s + 1) & 1) * STAGE;
        if (s + 1 < STAGES) {
            CP_B(nxt, (s + 1) * BK);
            LOAD_A((s + 1) * BK);
        }

        // ---- compute stage s: A frags (2 m-tiles x 2 splits), 4 n-tile-pairs
        u32 afr[2][2][4];
        #pragma unroll
        for (int mt = 0; mt < 2; mt++)
            #pragma unroll
            for (int sp = 0; sp < 2; sp++)
                ldsm_x4(afr[mt][sp][0], afr[mt][sp][1], afr[mt][sp][2], afr[mt][sp][3],
                        cur + sp*ACOMP + (a_r + mt*16)*ROWB + a_ch*16);

        #pragma unroll
        for (int ntp = 0; ntp < 4; ntp++) {
            u32 bfr[2][2][2];                 // [which nt of pair][split][2 regs]
            #pragma unroll
            for (int sp = 0; sp < 2; sp++)
                ldsm_x4(bfr[0][sp][0], bfr[0][sp][1], bfr[1][sp][0], bfr[1][sp][1],
                        cur + BOFF + sp*ACOMP + (b_row + ntp*16)*ROWB + b_ch*16);
            #pragma unroll
            for (int h = 0; h < 2; h++) {
                const int nt = 2*ntp + h;
                #pragma unroll
                for (int mt = 0; mt < 2; mt++) {
                    float* c = &acc[(mt*8 + nt)*4];
                    mma16816(c, afr[mt][0], bfr[h][0]);   // a0*b0
                    mma16816(c, afr[mt][0], bfr[h][1]);   // a0*b1
                    mma16816(c, afr[mt][1], bfr[h][0]);   // a1*b0
                    mma16816(c, afr[mt][1], bfr[h][1]);   // a1*b1
                }
            }
        }

        if (s + 1 < STAGES) {
            STS_A(nxt);
            CPWAIT0();
        }
        __syncthreads();
    }

    // ---- epilogue: accs -> smem (reuse stage memory), then GCN agg + bias + relu
    float* Ds = (float*)smem;            // [128][132]
    {
        const int r0 = wm*32 + (lane >> 2);
        const int c0 = wn*64 + (lane & 3)*2;
        #pragma unroll
        for (int mt = 0; mt < 2; mt++)
            #pragma unroll
            for (int nt = 0; nt < 8; nt++) {
                const float* c = &acc[(mt*8 + nt)*4];
                float* d = &Ds[(size_t)(r0 + mt*16)*132 + c0 + nt*8];
                d[0] = c[0]; d[1] = c[1];
                d[132*8 + 0] = c[2]; d[132*8 + 1] = c[3];
            }
    }
    __syncthreads();

    {
        const int g  = tid >> 4;         // graph in tile (16)
        const int cg = tid & 15;         // 8-col group (16)
        float gv[7][8];
        #pragma unroll
        for (int i = 0; i < 7; i++) {
            float4 lo = *(float4*)&Ds[(size_t)(g*8 + i)*132 + cg*8];
            float4 hi = *(float4*)&Ds[(size_t)(g*8 + i)*132 + cg*8 + 4];
            gv[i][0]=lo.x; gv[i][1]=lo.y; gv[i][2]=lo.z; gv[i][3]=lo.w;
            gv[i][4]=hi.x; gv[i][5]=hi.y; gv[i][6]=hi.z; gv[i][7]=hi.w;
        }
        float dinv[7];
        #pragma unroll
        for (int j = 0; j < 7; j++) dinv[j] = rsqrtf((float)(j + 1));
        float bv[8];
        #pragma unroll
        for (int c = 0; c < 8; c++) bv[c] = bias[n0 + cg*8 + c];

        const size_t ob = (size_t)(m0 + g*8) * HID + n0 + cg*8;
        #pragma unroll
        for (int j = 0; j < 7; j++) {
            float o[8];
            #pragma unroll
            for (int c = 0; c < 8; c++) o[c] = 0.f;
            #pragma unroll
            for (int i = 0; i < 7; i++) {
                if (i <= j) {
                    float cji = dinv[i] * dinv[j] * INV_WSCALE;   // undo 64x W scaling
                    #pragma unroll
                    for (int c = 0; c < 8; c++) o[c] = fmaf(cji, gv[i][c], o[c]);
                }
            }
            float4 s0, s1;
            s0.x = fmaxf(o[0]+bv[0], 0.f); s0.y = fmaxf(o[1]+bv[1], 0.f);
            s0.z = fmaxf(o[2]+bv[2], 0.f); s0.w = fmaxf(o[3]+bv[3], 0.f);
            s1.x = fmaxf(o[4]+bv[4], 0.f); s1.y = fmaxf(o[5]+bv[5], 0.f);
            s1.z = fmaxf(o[6]+bv[6], 0.f); s1.w = fmaxf(o[7]+bv[7], 0.f);
            *(float4*)&H[ob + (size_t)j * HID]     = s0;
            *(float4*)&H[ob + (size_t)j * HID + 4] = s1;
        }
    }
    #undef LOAD_A
    #undef STS_A
    #undef CP_B
}

// ============ W -> 2-way fp16 split of 64*W, transposed to [n][k] ====================
__global__ void w_prep(const float* __restrict__ W1, const float* __restrict__ W2)
{
    const int layer = blockIdx.y;
    const float* W = layer ? W2 : W1;
    __half* O = g_Wsp[layer];
    const int k = blockIdx.x;
    const int n = threadIdx.x;
    float w = W[(size_t)k * HID + n] * WSCALE;     // scale into fp16 normal range
    __half c0 = __float2half_rn(w);
    float r = w - __half2float(c0);
    __half c1 = __float2half_rn(r);
    size_t o = (size_t)n * HID + k;
    O[o]             = c0;
    O[HID*HID + o]   = c1;
}

// ============ final op projection (warp-per-node) + weighted agg + hard argmax =========
// 896 threads = 28 warps = 4 graphs per block; grid = NGR/4
__global__ __launch_bounds__(896)
void op_select(const float* __restrict__ Wm, const float* __restrict__ bm,
               const float* __restrict__ gop, float* __restrict__ out)
{
    __shared__ float Wms[HID * NOPS];
    __shared__ float qs[28][NOPS];

    const int tid = threadIdx.x;
    for (int i = tid; i < HID * NOPS; i += 896) Wms[i] = Wm[i];
    __syncthreads();

    const int warp = tid >> 5;           // 0..27
    const int lane = tid & 31;
    const int lg   = warp / 7;           // local graph 0..3
    const int j    = warp - lg * 7;      // node within graph
    const int g    = blockIdx.x * 4 + lg;

    // coalesced row read: lane covers k = lane*8 .. lane*8+7
    const size_t prow = (size_t)g * PAD + j;
    const float4* row = (const float4*)(g_H2p + prow * HID);
    float4 h0 = row[lane*2], h1 = row[lane*2 + 1];

    float q[NOPS] = {0.f,0.f,0.f,0.f,0.f};
    const float* w = &Wms[lane * 8 * NOPS];
    #pragma unroll
    for (int o = 0; o < NOPS; o++) q[o] = fmaf(h0.x, w[0*NOPS+o], q[o]);
    #pragma unroll
    for (int o = 0; o < NOPS; o++) q[o] = fmaf(h0.y, w[1*NOPS+o], q[o]);
    #pragma unroll
    for (int o = 0; o < NOPS; o++) q[o] = fmaf(h0.z, w[2*NOPS+o], q[o]);
    #pragma unroll
    for (int o = 0; o < NOPS; o++) q[o] = fmaf(h0.w, w[3*NOPS+o], q[o]);
    #pragma unroll
    for (int o = 0; o < NOPS; o++) q[o] = fmaf(h1.x, w[4*NOPS+o], q[o]);
    #pragma unroll
    for (int o = 0; o < NOPS; o++) q[o] = fmaf(h1.y, w[5*NOPS+o], q[o]);
    #pragma unroll
    for (int o = 0; o < NOPS; o++) q[o] = fmaf(h1.z, w[6*NOPS+o], q[o]);
    #pragma unroll
    for (int o = 0; o < NOPS; o++) q[o] = fmaf(h1.w, w[7*NOPS+o], q[o]);

    #pragma unroll
    for (int off = 16; off; off >>= 1)
        #pragma unroll
        for (int o = 0; o < NOPS; o++)
            q[o] += __shfl_xor_sync(0xFFFFFFFFu, q[o], off);

    if (lane == 0)
        #pragma unroll
        for (int o = 0; o < NOPS; o++) qs[warp][o] = q[o];
    __syncthreads();

    // threads 0..27: one per node — aggregation + gumbel argmax + one-hot write
    if (tid < 28) {
        const int lg2 = tid / 7;
        const int jj  = tid - lg2 * 7;
        const int node = (blockIdx.x * 4 + lg2) * 7 + jj;

        float p[NOPS];
        #pragma unroll
        for (int o = 0; o < NOPS; o++) p[o] = bm[o];
        const float dj = rsqrtf(1.f + 0.5f * (float)jj);
        for (int i = 0; i <= jj; i++) {
            float c = rsqrtf(1.f + 0.5f * (float)i) * dj;
            if (i != jj) c *= 0.5f;
            #pragma unroll
            for (int o = 0; o < NOPS; o++) p[o] += c * qs[lg2*7 + i][o];
        }

        float best = -3.4e38f; int arg = 0;
        #pragma unroll
        for (int o = 0; o < NOPS; o++) {
            float z = p[o] + gop[(size_t)node * NOPS + o];
            if (z > best) { best = z; arg = o; }   // strict > keeps FIRST max (jnp.argmax)
        }
        #pragma unroll
        for (int o = 0; o < NOPS; o++)
            out[(size_t)node * NOPS + o] = (o == arg) ? 1.0f : 0.0f;
    }
}

extern "C" void kernel_launch(void* const* d_in, const int* in_sizes, int n_in,
                              void* d_out, int out_size)
{
    const float* x   = (const float*)d_in[0];
    const float* W1  = (const float*)d_in[3];
    const float* b1  = (const float*)d_in[4];
    const float* W2  = (const float*)d_in[5];
    const float* b2  = (const float*)d_in[6];
    const float* Wm  = (const float*)d_in[9];
    const float* bm  = (const float*)d_in[10];
    const float* gop = (const float*)d_in[12];
    float* out = (float*)d_out;

    float *H1p, *H2p;
    __half* Wsp;
    cudaGetSymbolAddress((void**)&H1p, g_H1p);
    cudaGetSymbolAddress((void**)&H2p, g_H2p);
    cudaGetSymbolAddress((void**)&Wsp, g_Wsp);

    cudaFuncSetAttribute(gemm_mma, cudaFuncAttributeMaxDynamicSharedMemorySize, SMEM_DYN);

    w_prep<<<dim3(HID, 2), HID>>>(W1, W2);

    dim3 grid(HID / BN, MP / BM);        // (2, 1250)
    gemm_mma<<<grid, 256, SMEM_DYN>>>(x,   Wsp,             b1, H1p, 1);
    gemm_mma<<<grid, 256, SMEM_DYN>>>(H1p, Wsp + 2*HID*HID, b2, H2p, 0);

    op_select<<<NGR / 4, 896>>>(Wm, bm, gop, out);
}

// round 8
// speedup vs baseline: 1.0141x; 1.0141x over previous
#include <cuda_runtime.h>
#include <cuda_bf16.h>
#include <cstdint>

#define NGR   20000
#define NODES 7
#define PAD   8
#define MP    (NGR*PAD)        // 160000 padded rows
#define NN    (NGR*NODES)      // 140000 real nodes
#define HID   256
#define NOPS  5

#define BM 128                 // 16 graphs (8 padded rows each)
#define BN 128
#define BK 16
#define STAGES (HID/BK)        // 16
#define NPIPE  3

#define ROWB  48               // bytes per smem row (16 bf16 data + 16 pad; conflict-free)
#define ACOMP (128*ROWB)       // 6144 B per split component
#define BOFF  (3*ACOMP)        // A planes 0..2, then B planes 0..2
#define STAGE (6*ACOMP)        // 36864 per stage
#define SMEM_DYN (NPIPE*STAGE) // 110592 (also covers 128x132 fp32 epilogue staging = 67584)

// ---------------- device globals (no allocs allowed) ----------------
__device__ float g_H2p[(size_t)MP*HID];                  // padded fp32 layer-2 output
__device__ __nv_bfloat16 g_Asp [(size_t)3*MP*HID];       // bf16x3 planes of padded X
__device__ __nv_bfloat16 g_H1sp[(size_t)3*MP*HID];       // bf16x3 planes of padded H1
__device__ __nv_bfloat16 g_Wsp[2][3*HID*HID];            // per-layer bf16x3 of W, [n][k]

typedef uint32_t u32;

// ---------------- PTX helpers (plain sm_80-class features only) ----------------
__device__ __forceinline__ u32 s2u(const void* p){
    u32 a;
    asm("{ .reg .u64 t; cvta.to.shared.u64 t, %1; cvt.u32.u64 %0, t; }" : "=r"(a) : "l"(p));
    return a;
}
__device__ __forceinline__ void cp16(u32 dst, const void* src){
    asm volatile("cp.async.cg.shared.global [%0], [%1], 16;" :: "r"(dst), "l"(src));
}
#define CPCOMMIT() asm volatile("cp.async.commit_group;")
#define CPWAIT(n)  asm volatile("cp.async.wait_group %0;" :: "n"(n) : "memory")

__device__ __forceinline__ void ldsm_x4(u32& r0,u32& r1,u32& r2,u32& r3, u32 a){
    asm volatile("ldmatrix.sync.aligned.m8n8.x4.shared.b16 {%0,%1,%2,%3}, [%4];"
                 : "=r"(r0),"=r"(r1),"=r"(r2),"=r"(r3) : "r"(a));
}
__device__ __forceinline__ void ldsm_x2(u32& r0,u32& r1, u32 a){
    asm volatile("ldmatrix.sync.aligned.m8n8.x2.shared.b16 {%0,%1}, [%2];"
                 : "=r"(r0),"=r"(r1) : "r"(a));
}
__device__ __forceinline__ void mma16816(float* c, const u32* a, const u32* b){
    asm volatile("mma.sync.aligned.m16n8k16.row.col.f32.bf16.bf16.f32 "
        "{%0,%1,%2,%3}, {%4,%5,%6,%7}, {%8,%9}, {%0,%1,%2,%3};"
        : "+f"(c[0]),"+f"(c[1]),"+f"(c[2]),"+f"(c[3])
        : "r"(a[0]),"r"(a[1]),"r"(a[2]),"r"(a[3]), "r"(b[0]),"r"(b[1]));
}
// fp32 -> 3-way bf16 split of adjacent pair (lo=x, hi=y), packed bf16x2
__device__ __forceinline__ void split2(float x, float y, u32& p0, u32& p1, u32& p2){
    asm("cvt.rn.bf16x2.f32 %0, %1, %2;" : "=r"(p0) : "f"(y), "f"(x));
    float rx = x - __uint_as_float(p0 << 16);
    float ry = y - __uint_as_float(p0 & 0xFFFF0000u);
    asm("cvt.rn.bf16x2.f32 %0, %1, %2;" : "=r"(p1) : "f"(ry), "f"(rx));
    float qx = rx - __uint_as_float(p1 << 16);
    float qy = ry - __uint_as_float(p1 & 0xFFFF0000u);
    asm("cvt.rn.bf16x2.f32 %0, %1, %2;" : "=r"(p2) : "f"(qy), "f"(qx));
}

// ============ X -> padded bf16x3 planes ============
__global__ __launch_bounds__(256)
void split_x(const float* __restrict__ x)
{
    const int g = blockIdx.x, t = threadIdx.x;
    const int cp = (t & 127) * 2;      // column pair base
    const int rh = t >> 7;             // row half 0/1
    #pragma unroll
    for (int rr = 0; rr < 4; rr++) {
        int row = rr*2 + rh;           // 0..7
        u32 p0 = 0, p1 = 0, p2 = 0;
        if (row < NODES) {
            const float* s = x + ((size_t)g*NODES + row) * HID + cp;
            split2(s[0], s[1], p0, p1, p2);
        }
        size_t o = ((size_t)g*PAD + row) * HID + cp;
        *(u32*)(g_Asp + o)                      = p0;
        *(u32*)(g_Asp + (size_t)MP*HID + o)     = p1;
        *(u32*)(g_Asp + (size_t)2*MP*HID + o)   = p2;
    }
}

// ============ HMMA GEMM (bf16x3 6-pass), pure cp.async pipeline ============
// out_fp32=0: epilogue writes H as bf16x3 planes (Hsp). out_fp32=1: writes fp32 (Hf).
__global__ __launch_bounds__(256, 2)
void gemm_mma(const __nv_bfloat16* __restrict__ Asp, const __nv_bfloat16* __restrict__ Bsp,
              const float* __restrict__ bias, float* __restrict__ Hf,
              __nv_bfloat16* __restrict__ Hsp, int out_fp32)
{
    extern __shared__ __align__(128) char smem[];
    const u32 sb = s2u(smem);

    const int tid  = threadIdx.x;
    const int lane = tid & 31;
    const int warp = tid >> 5;
    const int wm = warp >> 1;          // 0..3  (M: 32-row slab)
    const int wn = warp & 1;           // 0..1  (N: 64-col slab)
    const int m0 = blockIdx.y * BM;
    const int n0 = blockIdx.x * BN;

    // 6 cp.async(16B) per thread per stage: 3 A-plane chunks + 3 B-plane chunks
    #define CP_STAGE(stb, k0) do {                                              \
        _Pragma("unroll")                                                       \
        for (int i = 0; i < 3; i++) {                                           \
            int c = tid + 256*i;                                                \
            int comp = c >> 8, rem = c & 255, r = rem >> 1, hf = rem & 1;       \
            cp16((stb) + comp*ACOMP + r*ROWB + hf*16,                           \
                 Asp + (size_t)comp*((size_t)MP*HID)                            \
                     + (size_t)(m0 + r)*HID + (k0) + hf*8);                     \
        }                                                                       \
        _Pragma("unroll")                                                       \
        for (int i = 0; i < 3; i++) {                                           \
            int c = tid + 256*i;                                                \
            int comp = c >> 8, rem = c & 255, r = rem >> 1, hf = rem & 1;       \
            cp16((stb) + BOFF + comp*ACOMP + r*ROWB + hf*16,                    \
                 Bsp + (size_t)comp*(HID*HID)                                   \
                     + (size_t)(n0 + r)*HID + (k0) + hf*8);                     \
        }                                                                       \
        CPCOMMIT();                                                             \
    } while(0)

    // prologue: stages 0,1 in flight
    CP_STAGE(sb,          0);
    CP_STAGE(sb + STAGE,  BK);

    float acc[64];
    #pragma unroll
    for (int i = 0; i < 64; i++) acc[i] = 0.f;

    const int a_r  = wm*32 + (lane & 15);
    const int a_ch = lane >> 4;
    const int b_r  = wn*64 + (lane & 7);
    const int b_ch = (lane >> 3) & 1;

    #pragma unroll 1
    for (int s = 0; s < STAGES; s++) {
        CPWAIT(1);                      // stage s landed (s+1 may still fly)
        __syncthreads();                // all warps done with stage s-1's buffer
        if (s + 2 < STAGES) {
            const u32 nb = sb + (u32)((s + 2) % NPIPE) * STAGE;   // held s-1: free
            CP_STAGE(nb, (s + 2) * BK);
        } else {
            CPCOMMIT();                 // empty group keeps wait arithmetic constant
        }

        const u32 cur = sb + (u32)(s % NPIPE) * STAGE;

        u32 afr[2][3][4];
        #pragma unroll
        for (int mt = 0; mt < 2; mt++)
            #pragma unroll
            for (int sp = 0; sp < 3; sp++)
                ldsm_x4(afr[mt][sp][0], afr[mt][sp][1], afr[mt][sp][2], afr[mt][sp][3],
                        cur + sp*ACOMP + (a_r + mt*16)*ROWB + a_ch*16);

        #pragma unroll
        for (int nt = 0; nt < 8; nt++) {
            u32 bfr[3][2];
            #pragma unroll
            for (int sp = 0; sp < 3; sp++)
                ldsm_x2(bfr[sp][0], bfr[sp][1],
                        cur + BOFF + sp*ACOMP + (b_r + nt*8)*ROWB + b_ch*16);
            #pragma unroll
            for (int mt = 0; mt < 2; mt++) {
                float* c = &acc[(mt*8 + nt)*4];
                mma16816(c, afr[mt][0], bfr[0]);   // a0*b0
                mma16816(c, afr[mt][0], bfr[1]);   // a0*b1
                mma16816(c, afr[mt][1], bfr[0]);   // a1*b0
                mma16816(c, afr[mt][1], bfr[1]);   // a1*b1
                mma16816(c, afr[mt][0], bfr[2]);   // a0*b2
                mma16816(c, afr[mt][2], bfr[0]);   // a2*b0
            }
        }
    }
    __syncthreads();                    // last stage consumed before Ds overwrite

    // ---- epilogue: accs -> smem, GCN agg + bias + relu, store
    float* Ds = (float*)smem;           // [128][132]
    {
        const int r0 = wm*32 + (lane >> 2);
        const int c0 = wn*64 + (lane & 3)*2;
        #pragma unroll
        for (int mt = 0; mt < 2; mt++)
            #pragma unroll
            for (int nt = 0; nt < 8; nt++) {
                const float* c = &acc[(mt*8 + nt)*4];
                float* d = &Ds[(size_t)(r0 + mt*16)*132 + c0 + nt*8];
                d[0] = c[0]; d[1] = c[1];
                d[132*8 + 0] = c[2]; d[132*8 + 1] = c[3];
            }
    }
    __syncthreads();

    {
        const int g  = tid >> 4;        // graph in tile (16)
        const int cg = tid & 15;        // 8-col group (16)
        float gv[7][8];
        #pragma unroll
        for (int i = 0; i < 7; i++) {
            float4 lo = *(float4*)&Ds[(size_t)(g*8 + i)*132 + cg*8];
            float4 hi = *(float4*)&Ds[(size_t)(g*8 + i)*132 + cg*8 + 4];
            gv[i][0]=lo.x; gv[i][1]=lo.y; gv[i][2]=lo.z; gv[i][3]=lo.w;
            gv[i][4]=hi.x; gv[i][5]=hi.y; gv[i][6]=hi.z; gv[i][7]=hi.w;
        }
        float dinv[7];
        #pragma unroll
        for (int j = 0; j < 7; j++) dinv[j] = rsqrtf((float)(j + 1));
        float bv[8];
        #pragma unroll
        for (int c = 0; c < 8; c++) bv[c] = bias[n0 + cg*8 + c];

        #pragma unroll
        for (int j = 0; j < 7; j++) {
            float v[8];
            #pragma unroll
            for (int c = 0; c < 8; c++) v[c] = 0.f;
            #pragma unroll
            for (int i = 0; i < 7; i++) {
                if (i <= j) {
                    float cji = dinv[i] * dinv[j];
                    #pragma unroll
                    for (int c = 0; c < 8; c++) v[c] = fmaf(cji, gv[i][c], v[c]);
                }
            }
            #pragma unroll
            for (int c = 0; c < 8; c++) v[c] = fmaxf(v[c] + bv[c], 0.f);

            const size_t ob = (size_t)(m0 + g*8 + j) * HID + n0 + cg*8;
            if (out_fp32) {
                *(float4*)&Hf[ob]     = make_float4(v[0], v[1], v[2], v[3]);
                *(float4*)&Hf[ob + 4] = make_float4(v[4], v[5], v[6], v[7]);
            } else {
                u32 q0[4], q1[4], q2[4];
                split2(v[0], v[1], q0[0], q1[0], q2[0]);
                split2(v[2], v[3], q0[1], q1[1], q2[1]);
                split2(v[4], v[5], q0[2], q1[2], q2[2]);
                split2(v[6], v[7], q0[3], q1[3], q2[3]);
                *(uint4*)(Hsp + ob)                    = make_uint4(q0[0],q0[1],q0[2],q0[3]);
                *(uint4*)(Hsp + (size_t)MP*HID + ob)   = make_uint4(q1[0],q1[1],q1[2],q1[3]);
                *(uint4*)(Hsp + (size_t)2*MP*HID + ob) = make_uint4(q2[0],q2[1],q2[2],q2[3]);
            }
        }
        if (!out_fp32) {                // pad row 7 must be zero for layer-2 loads
            const size_t ob = (size_t)(m0 + g*8 + 7) * HID + n0 + cg*8;
            uint4 z = make_uint4(0,0,0,0);
            *(uint4*)(Hsp + ob)                    = z;
            *(uint4*)(Hsp + (size_t)MP*HID + ob)   = z;
            *(uint4*)(Hsp + (size_t)2*MP*HID + ob) = z;
        }
    }
    #undef CP_STAGE
}

// ============ W -> 3-way bf16 split, transposed to [n][k] ====================
__global__ void w_prep(const float* __restrict__ W1, const float* __restrict__ W2)
{
    const int layer = blockIdx.y;
    const float* W = layer ? W2 : W1;
    __nv_bfloat16* O = g_Wsp[layer];
    const int k = blockIdx.x;
    const int n = threadIdx.x;
    float w = W[(size_t)k * HID + n];
    __nv_bfloat16 c0 = __float2bfloat16_rn(w);
    float r = w - __bfloat162float(c0);
    __nv_bfloat16 c1 = __float2bfloat16_rn(r);
    float r2 = r - __bfloat162float(c1);
    __nv_bfloat16 c2 = __float2bfloat16_rn(r2);
    size_t o = (size_t)n * HID + k;
    O[o]               = c0;
    O[HID*HID + o]     = c1;
    O[2*HID*HID + o]   = c2;
}

// ============ final op projection + weighted agg + hard argmax (R6 version) ==========
__global__ __launch_bounds__(224)
void op_select(const float* __restrict__ Wm, const float* __restrict__ bm,
               const float* __restrict__ gop, float* __restrict__ out)
{
    __shared__ float Wms[HID * NOPS];
    __shared__ float qs[224][NOPS];

    const int tid = threadIdx.x;
    for (int i = tid; i < HID * NOPS; i += 224) Wms[i] = Wm[i];
    __syncthreads();

    const int node = blockIdx.x * 224 + tid;
    const int lg = tid / 7;
    const int j  = tid - lg * 7;
    const size_t prow = ((size_t)(node / 7)) * PAD + (node % 7);

    const float4* row = (const float4*)(g_H2p + prow * HID);
    float q[NOPS] = {0.f, 0.f, 0.f, 0.f, 0.f};
    #pragma unroll 4
    for (int k4 = 0; k4 < HID/4; k4++) {
        float4 h = row[k4];
        const float* w = &Wms[k4 * 4 * NOPS];
        #pragma unroll
        for (int o = 0; o < NOPS; o++) q[o] = fmaf(h.x, w[o],          q[o]);
        #pragma unroll
        for (int o = 0; o < NOPS; o++) q[o] = fmaf(h.y, w[NOPS + o],   q[o]);
        #pragma unroll
        for (int o = 0; o < NOPS; o++) q[o] = fmaf(h.z, w[2*NOPS + o], q[o]);
        #pragma unroll
        for (int o = 0; o < NOPS; o++) q[o] = fmaf(h.w, w[3*NOPS + o], q[o]);
    }
    #pragma unroll
    for (int o = 0; o < NOPS; o++) qs[tid][o] = q[o];
    __syncthreads();

    float p[NOPS];
    #pragma unroll
    for (int o = 0; o < NOPS; o++) p[o] = bm[o];
    const float dj = rsqrtf(1.f + 0.5f * (float)j);
    for (int i = 0; i <= j; i++) {
        float c = rsqrtf(1.f + 0.5f * (float)i) * dj;
        if (i != j) c *= 0.5f;
        #pragma unroll
        for (int o = 0; o < NOPS; o++) p[o] += c * qs[lg*7 + i][o];
    }

    float best = -3.4e38f; int arg = 0;
    #pragma unroll
    for (int o = 0; o < NOPS; o++) {
        float z = p[o] + gop[(size_t)node * NOPS + o];
        if (z > best) { best = z; arg = o; }   // strict > keeps FIRST max (jnp.argmax)
    }
    #pragma unroll
    for (int o = 0; o < NOPS; o++)
        out[(size_t)node * NOPS + o] = (o == arg) ? 1.0f : 0.0f;
}

extern "C" void kernel_launch(void* const* d_in, const int* in_sizes, int n_in,
                              void* d_out, int out_size)
{
    const float* x   = (const float*)d_in[0];
    const float* W1  = (const float*)d_in[3];
    const float* b1  = (const float*)d_in[4];
    const float* W2  = (const float*)d_in[5];
    const float* b2  = (const float*)d_in[6];
    const float* Wm  = (const float*)d_in[9];
    const float* bm  = (const float*)d_in[10];
    const float* gop = (const float*)d_in[12];
    float* out = (float*)d_out;

    float* H2p;
    __nv_bfloat16 *Asp, *H1sp, *Wsp;
    cudaGetSymbolAddress((void**)&H2p,  g_H2p);
    cudaGetSymbolAddress((void**)&Asp,  g_Asp);
    cudaGetSymbolAddress((void**)&H1sp, g_H1sp);
    cudaGetSymbolAddress((void**)&Wsp,  g_Wsp);

    cudaFuncSetAttribute(gemm_mma, cudaFuncAttributeMaxDynamicSharedMemorySize, SMEM_DYN);

    split_x<<<NGR, 256>>>(x);
    w_prep<<<dim3(HID, 2), HID>>>(W1, W2);

    dim3 grid(HID / BN, MP / BM);        // (2, 1250)
    gemm_mma<<<grid, 256, SMEM_DYN>>>(Asp,  Wsp,             b1, nullptr, H1sp,  0);
    gemm_mma<<<grid, 256, SMEM_DYN>>>(H1sp, Wsp + 3*HID*HID, b2, H2p,     nullptr, 1);

    op_select<<<NN / 224, 224>>>(Wm, bm, gop, out);
}